// round 5
// baseline (speedup 1.0000x reference)
#include <cuda_runtime.h>
#include <math.h>

// Problem constants
#define NB    256   // batch
#define TP    32    // past length
#define TFUT  256   // future length
#define HH    100   // hidden H
#define HFF   275   // field hidden
#define HGG   75
#define HOO   75
#define K1    101   // H+1
#define K1P   104   // padded to /4
#define K2P   276   // 275 padded to /4

#define NTHR  288   // 9 warps
#define NCTA  128   // CTAs for encode/rollout (2 rows each)

// -------- device scratch (no allocations allowed) --------
__device__ __align__(16) float g_pW1[HFF * K1P];
__device__ __align__(16) float g_pW2[HFF * K2P];
__device__ __align__(16) float g_pW3[HH  * K2P];
__device__ float g_hB[NB * HH];
__device__ float g_gx[NB * 2];
__device__ float g_z0[NB * HH];

__device__ __forceinline__ float leaky1(float x) {
    const float SL = 1.0f / 5.5f;
    return x >= 0.f ? x : x * SL;
}
__device__ __forceinline__ float sigm1(float x) {
    return 1.f / (1.f + expf(-x));
}

// Dot of one weight row (length 4*NITER, padded with zeros) against a
// row-pair activation vector stored as float2[k] = (row0, row1).
// 8 independent accumulator chains for FMA-latency hiding.
template<int NITER, bool STREAM>
__device__ __forceinline__ float2 dot_row(const float* __restrict__ Wrow,
                                          const float2* __restrict__ xin,
                                          float bias) {
    const float4* wr = reinterpret_cast<const float4*>(Wrow);
    const float4* xr = reinterpret_cast<const float4*>(xin);
    float a00 = bias, a01 = 0.f, a02 = 0.f, a03 = 0.f;
    float a10 = bias, a11 = 0.f, a12 = 0.f, a13 = 0.f;
#pragma unroll 4
    for (int i = 0; i < NITER; i++) {
        float4 w = STREAM ? __ldcs(wr + i) : __ldg(wr + i);
        float4 p = xr[2 * i];       // (x[4i].r0, x[4i].r1, x[4i+1].r0, x[4i+1].r1)
        float4 q = xr[2 * i + 1];   // (x[4i+2].r0, ...)
        a00 = fmaf(w.x, p.x, a00);  a10 = fmaf(w.x, p.y, a10);
        a01 = fmaf(w.y, p.z, a01);  a11 = fmaf(w.y, p.w, a11);
        a02 = fmaf(w.z, q.x, a02);  a12 = fmaf(w.z, q.y, a12);
        a03 = fmaf(w.w, q.z, a03);  a13 = fmaf(w.w, q.w, a13);
    }
    return make_float2((a00 + a01) + (a02 + a03), (a10 + a11) + (a12 + a13));
}

// Field MLP: s_in (101 used, padded zeros at 101..103, pad slot 275) -> s_f.
// Ping-pong: L1: s_in->s_hid, L2: s_hid->s_in, L3: s_in->s_f.
// Caller must __syncthreads() after building s_in. Returns synced.
__device__ __forceinline__ void field_eval(int tid,
        float2* s_in, float2* s_hid, float2* s_f,
        const float* __restrict__ fb1, const float* __restrict__ fb2,
        const float* __restrict__ fb3) {
    if (tid < HFF) {
        float2 a = dot_row<K1P / 4, false>(g_pW1 + tid * K1P, s_in, __ldg(fb1 + tid));
        s_hid[tid] = make_float2(tanhf(a.x), tanhf(a.y));
    }
    __syncthreads();
    if (tid < HFF) {
        float2 a = dot_row<K2P / 4, true>(g_pW2 + tid * K2P, s_hid, __ldg(fb2 + tid));
        s_in[tid] = make_float2(tanhf(a.x), tanhf(a.y));
    }
    __syncthreads();
    if (tid < HH) {
        float2 a = dot_row<K2P / 4, false>(g_pW3 + tid * K2P, s_in, __ldg(fb3 + tid));
        s_f[tid] = make_float2(tanhf(a.x), tanhf(a.y));
    }
    __syncthreads();
}

// RK4 with NSUB=2 substeps: y (s_y) advanced from t0 to t1 (per-row times).
__device__ __forceinline__ void integrate2(int tid, float2 t0, float2 t1,
        float2* s_in, float2* s_hid, float2* s_y, float2* s_ks, float2* s_f,
        const float* __restrict__ fb1, const float* __restrict__ fb2,
        const float* __restrict__ fb3) {
    float2 dt = make_float2((t1.x - t0.x) * 0.5f, (t1.y - t0.y) * 0.5f);
#pragma unroll 1
    for (int sub = 0; sub < 2; sub++) {
        float2 t  = make_float2(t0.x + (float)sub * dt.x, t0.y + (float)sub * dt.y);
        float2 th = make_float2(t.x + 0.5f * dt.x, t.y + 0.5f * dt.y);
        float2 te = make_float2(t.x + dt.x, t.y + dt.y);

        // stage 1: x = [t, y]
        if (tid < HH)        s_in[1 + tid] = s_y[tid];
        else if (tid < 103)  s_in[1 + tid] = make_float2(0.f, 0.f);
        if (tid == 0)        s_in[0] = t;
        __syncthreads();
        field_eval(tid, s_in, s_hid, s_f, fb1, fb2, fb3);            // k1
        if (tid < HH) {
            float2 f = s_f[tid], y = s_y[tid];
            s_ks[tid] = f;
            s_in[1 + tid] = make_float2(fmaf(0.5f * dt.x, f.x, y.x),
                                        fmaf(0.5f * dt.y, f.y, y.y));
        } else if (tid < 103) s_in[1 + tid] = make_float2(0.f, 0.f);
        if (tid == 0) s_in[0] = th;
        __syncthreads();
        field_eval(tid, s_in, s_hid, s_f, fb1, fb2, fb3);            // k2
        if (tid < HH) {
            float2 f = s_f[tid], y = s_y[tid], k = s_ks[tid];
            s_ks[tid] = make_float2(k.x + 2.f * f.x, k.y + 2.f * f.y);
            s_in[1 + tid] = make_float2(fmaf(0.5f * dt.x, f.x, y.x),
                                        fmaf(0.5f * dt.y, f.y, y.y));
        } else if (tid < 103) s_in[1 + tid] = make_float2(0.f, 0.f);
        if (tid == 0) s_in[0] = th;
        __syncthreads();
        field_eval(tid, s_in, s_hid, s_f, fb1, fb2, fb3);            // k3
        if (tid < HH) {
            float2 f = s_f[tid], y = s_y[tid], k = s_ks[tid];
            s_ks[tid] = make_float2(k.x + 2.f * f.x, k.y + 2.f * f.y);
            s_in[1 + tid] = make_float2(fmaf(dt.x, f.x, y.x),
                                        fmaf(dt.y, f.y, y.y));
        } else if (tid < 103) s_in[1 + tid] = make_float2(0.f, 0.f);
        if (tid == 0) s_in[0] = te;
        __syncthreads();
        field_eval(tid, s_in, s_hid, s_f, fb1, fb2, fb3);            // k4
        if (tid < HH) {
            float2 f = s_f[tid], y = s_y[tid], k = s_ks[tid];
            s_y[tid] = make_float2(y.x + dt.x * (k.x + f.x) / 6.f,
                                   y.y + dt.y * (k.y + f.y) / 6.f);
        }
        __syncthreads();
    }
}

// -------- prep: pad field weights to /4 strides, zero padding --------
__global__ void prep_kernel(const float* __restrict__ fW1,
                            const float* __restrict__ fW2,
                            const float* __restrict__ fW3) {
    int i = blockIdx.x * blockDim.x + threadIdx.x;
    if (i < HFF * K1P) {
        int n = i / K1P, k = i % K1P;
        g_pW1[i] = (k < K1) ? fW1[n * K1 + k] : 0.f;
    }
    int j = i - HFF * K1P;
    if (j >= 0 && j < HFF * K2P) {
        int n = j / K2P, k = j % K2P;
        g_pW2[j] = (k < HFF) ? fW2[n * HFF + k] : 0.f;
    }
    int l = i - HFF * K1P - HFF * K2P;
    if (l >= 0 && l < HH * K2P) {
        int n = l / K2P, k = l % K2P;
        g_pW3[l] = (k < HFF) ? fW3[n * HFF + k] : 0.f;
    }
}

// -------- encode: 32 steps of (ODE integrate + GRU) per row-pair --------
__global__ void __launch_bounds__(NTHR) encode_kernel(
        const float* __restrict__ past, const float* __restrict__ h0,
        const float* __restrict__ fb1, const float* __restrict__ fb2,
        const float* __restrict__ fb3,
        const float* __restrict__ Wih, const float* __restrict__ Whh,
        const float* __restrict__ bih, const float* __restrict__ bhh) {
    __shared__ __align__(16) float2 s_in[K2P];
    __shared__ __align__(16) float2 s_hid[K2P];
    __shared__ __align__(16) float2 s_y[HH];
    __shared__ float2 s_ks[HH], s_f[HH];
    __shared__ float2 s_u[200], s_inn[HH], s_hn[HH];

    int tid = threadIdx.x;
    int r0 = blockIdx.x * 2, r1 = r0 + 1;

    if (tid == 0) { s_in[K2P - 1] = make_float2(0.f, 0.f); s_hid[K2P - 1] = make_float2(0.f, 0.f); }
    if (tid < HH) s_y[tid] = make_float2(h0[r0 * HH + tid], h0[r1 * HH + tid]);
    __syncthreads();

    float2 tprev = make_float2(0.f, 0.f);
    for (int step = 0; step < TP; step++) {
        float2 tcur = make_float2(past[(r0 * TP + step) * 2], past[(r1 * TP + step) * 2]);
        float2 t0 = (step == 0) ? make_float2(tcur.x - 1.f, tcur.y - 1.f) : tprev;
        integrate2(tid, t0, tcur, s_in, s_hid, s_y, s_ks, s_f, fb1, fb2, fb3);

        // GRU (D = 1): gi[j] = Wih[j]*x + bih[j]; gh[j] = Whh[j]·h + bhh[j]
        float2 x = make_float2(past[(r0 * TP + step) * 2 + 1], past[(r1 * TP + step) * 2 + 1]);
        for (int jj = tid; jj < 3 * HH; jj += NTHR) {
            float wi = __ldg(Wih + jj);
            float bi = __ldg(bih + jj);
            float2 gi = make_float2(fmaf(wi, x.x, bi), fmaf(wi, x.y, bi));
            float2 a = dot_row<HH / 4, false>(Whh + jj * HH, s_y, __ldg(bhh + jj));
            if (jj < 2 * HH) s_u[jj] = make_float2(gi.x + a.x, gi.y + a.y);
            else { s_inn[jj - 2 * HH] = gi; s_hn[jj - 2 * HH] = a; }
        }
        __syncthreads();
        if (tid < HH) {
            float2 u1 = s_u[tid], u2 = s_u[HH + tid];
            float2 gin = s_inn[tid], ghn = s_hn[tid], h = s_y[tid];
            float rx = sigm1(u1.x), ry = sigm1(u1.y);
            float zx = sigm1(u2.x), zy = sigm1(u2.y);
            float nx = tanhf(gin.x + rx * ghn.x), ny = tanhf(gin.y + ry * ghn.y);
            s_y[tid] = make_float2((1.f - zx) * nx + zx * h.x,
                                   (1.f - zy) * ny + zy * h.y);
        }
        __syncthreads();
        tprev = tcur;
    }
    if (tid < HH) {
        g_hB[r0 * HH + tid] = s_y[tid].x;
        g_hB[r1 * HH + tid] = s_y[tid].y;
    }
}

// -------- decoder head: gx = MLP(h) per row --------
__global__ void gx_kernel(const float* __restrict__ gW1, const float* __restrict__ gb1,
                          const float* __restrict__ gW2, const float* __restrict__ gb2,
                          const float* __restrict__ gW3, const float* __restrict__ gb3) {
    int b = blockIdx.x, tid = threadIdx.x;
    __shared__ float sh[HH], s1[HGG], s2[HGG];
    for (int k = tid; k < HH; k += blockDim.x) sh[k] = g_hB[b * HH + k];
    __syncthreads();
    if (tid < HGG) {
        float a = __ldg(gb1 + tid);
        const float* w = gW1 + tid * HH;
        for (int k = 0; k < HH; k++) a = fmaf(__ldg(w + k), sh[k], a);
        s1[tid] = leaky1(a);
    }
    __syncthreads();
    if (tid < HGG) {
        float a = __ldg(gb2 + tid);
        const float* w = gW2 + tid * HGG;
        for (int k = 0; k < HGG; k++) a = fmaf(__ldg(w + k), s1[k], a);
        s2[tid] = leaky1(a);
    }
    __syncthreads();
    if (tid < 2) {
        float a = __ldg(gb3 + tid);
        const float* w = gW3 + tid * HGG;
        for (int k = 0; k < HGG; k++) a = fmaf(__ldg(w + k), s2[k], a);
        g_gx[b * 2 + tid] = a;
    }
}

// -------- z0: reparameterization with the concat/reshape shuffle --------
__global__ void z0_kernel(const float* __restrict__ eps) {
    int b = blockIdx.x, h = threadIdx.x;
    // v[j] = j<256 ? gx[j][0] : |gx[j-256][1]| ; loc[b]=v[2b], scale[b]=v[2b+1]
    float loc, scale;
    if (b < NB / 2) {
        loc   = g_gx[(2 * b) * 2 + 0];
        scale = g_gx[(2 * b + 1) * 2 + 0];
    } else {
        int i = 2 * (b - NB / 2);
        loc   = fabsf(g_gx[i * 2 + 1]);
        scale = fabsf(g_gx[(i + 1) * 2 + 1]);
    }
    g_z0[b * HH + h] = loc + scale * eps[h * NB + b];
}

// -------- rollout: 255 integrations + output MLP per step --------
__device__ __forceinline__ void out_mlp(int tid, int s, int r0, int r1,
        float2* s_in, float2* s_hid, const float2* s_y,
        const float* __restrict__ oW1, const float* __restrict__ ob1,
        const float* __restrict__ oW2, const float* __restrict__ ob2,
        const float* __restrict__ oW3, const float* __restrict__ ob3,
        float* __restrict__ out) {
    if (tid < HOO) {
        float2 a = dot_row<HH / 4, false>(oW1 + tid * HH, s_y, __ldg(ob1 + tid));
        s_hid[tid] = make_float2(leaky1(a.x), leaky1(a.y));
    }
    __syncthreads();
    if (tid < HOO) {
        float a0 = __ldg(ob2 + tid), a1 = a0;
        const float* w = oW2 + tid * HOO;
        for (int k = 0; k < HOO; k++) {
            float wv = __ldg(w + k);
            float2 h = s_hid[k];
            a0 = fmaf(wv, h.x, a0); a1 = fmaf(wv, h.y, a1);
        }
        s_in[tid] = make_float2(leaky1(a0), leaky1(a1));
    }
    __syncthreads();
    if (tid == 0) {
        float a0 = __ldg(ob3), a1 = a0;
        for (int k = 0; k < HOO; k++) {
            float wv = __ldg(oW3 + k);
            float2 h = s_in[k];
            a0 = fmaf(wv, h.x, a0); a1 = fmaf(wv, h.y, a1);
        }
        out[r0 * TFUT + s] = a0;
        out[r1 * TFUT + s] = a1;
    }
    __syncthreads();
}

__global__ void __launch_bounds__(NTHR) rollout_kernel(
        const float* __restrict__ tf_,
        const float* __restrict__ fb1, const float* __restrict__ fb2,
        const float* __restrict__ fb3,
        const float* __restrict__ oW1, const float* __restrict__ ob1,
        const float* __restrict__ oW2, const float* __restrict__ ob2,
        const float* __restrict__ oW3, const float* __restrict__ ob3,
        float* __restrict__ out) {
    __shared__ __align__(16) float2 s_in[K2P];
    __shared__ __align__(16) float2 s_hid[K2P];
    __shared__ __align__(16) float2 s_y[HH];
    __shared__ float2 s_ks[HH], s_f[HH];

    int tid = threadIdx.x;
    int r0 = blockIdx.x * 2, r1 = r0 + 1;

    if (tid == 0) { s_in[K2P - 1] = make_float2(0.f, 0.f); s_hid[K2P - 1] = make_float2(0.f, 0.f); }
    if (tid < HH) s_y[tid] = make_float2(g_z0[r0 * HH + tid], g_z0[r1 * HH + tid]);
    __syncthreads();

    // t = 0 output (z0 itself)
    out_mlp(tid, 0, r0, r1, s_in, s_hid, s_y, oW1, ob1, oW2, ob2, oW3, ob3, out);

    float2 tprev = make_float2(tf_[r0 * TFUT], tf_[r1 * TFUT]);
    for (int s = 1; s < TFUT; s++) {
        float2 tcur = make_float2(tf_[r0 * TFUT + s], tf_[r1 * TFUT + s]);
        integrate2(tid, tprev, tcur, s_in, s_hid, s_y, s_ks, s_f, fb1, fb2, fb3);
        out_mlp(tid, s, r0, r1, s_in, s_hid, s_y, oW1, ob1, oW2, ob2, oW3, ob3, out);
        tprev = tcur;
    }
}

extern "C" void kernel_launch(void* const* d_in, const int* in_sizes, int n_in,
                              void* d_out, int out_size) {
    const float* past = (const float*)d_in[0];
    const float* h0   = (const float*)d_in[1];
    const float* t_fu = (const float*)d_in[2];
    const float* eps  = (const float*)d_in[3];
    const float* fW1  = (const float*)d_in[4];
    const float* fb1  = (const float*)d_in[5];
    const float* fW2  = (const float*)d_in[6];
    const float* fb2  = (const float*)d_in[7];
    const float* fW3  = (const float*)d_in[8];
    const float* fb3  = (const float*)d_in[9];
    const float* Wih  = (const float*)d_in[10];
    const float* Whh  = (const float*)d_in[11];
    const float* bih  = (const float*)d_in[12];
    const float* bhh  = (const float*)d_in[13];
    const float* gW1  = (const float*)d_in[14];
    const float* gb1  = (const float*)d_in[15];
    const float* gW2  = (const float*)d_in[16];
    const float* gb2  = (const float*)d_in[17];
    const float* gW3  = (const float*)d_in[18];
    const float* gb3  = (const float*)d_in[19];
    const float* oW1  = (const float*)d_in[20];
    const float* ob1  = (const float*)d_in[21];
    const float* oW2  = (const float*)d_in[22];
    const float* ob2  = (const float*)d_in[23];
    const float* oW3  = (const float*)d_in[24];
    const float* ob3  = (const float*)d_in[25];
    float* out = (float*)d_out;

    const int prep_total = HFF * K1P + HFF * K2P + HH * K2P;
    prep_kernel<<<(prep_total + 255) / 256, 256>>>(fW1, fW2, fW3);
    encode_kernel<<<NCTA, NTHR>>>(past, h0, fb1, fb2, fb3, Wih, Whh, bih, bhh);
    gx_kernel<<<NB, 96>>>(gW1, gb1, gW2, gb2, gW3, gb3);
    z0_kernel<<<NB, HH>>>(eps);
    rollout_kernel<<<NCTA, NTHR>>>(t_fu, fb1, fb2, fb3,
                                   oW1, ob1, oW2, ob2, oW3, ob3, out);
}

// round 6
// speedup vs baseline: 1.0007x; 1.0007x over previous
#include <cuda_runtime.h>
#include <math.h>

// Problem constants
#define NB    256   // batch
#define TP    32    // past length
#define TFUT  256   // future length
#define HH    100   // hidden H
#define HFF   275   // field hidden
#define HGG   75
#define HOO   75
#define K1    101   // H+1
#define K1P   104   // padded to /4
#define K2P   276   // 275 padded to /4

#define NTHR  288   // 9 warps
#define NCTA  128   // CTAs for encode/rollout (2 rows each)

// -------- device scratch (no allocations allowed) --------
__device__ __align__(16) float g_pW1[HFF * K1P];
__device__ __align__(16) float g_pW2[HFF * K2P];
__device__ __align__(16) float g_pW3[HH  * K2P];
__device__ float g_hB[NB * HH];
__device__ float g_gx[NB * 2];
__device__ float g_z0[NB * HH];

__device__ __forceinline__ float leaky1(float x) {
    const float SL = 1.0f / 5.5f;
    return x >= 0.f ? x : x * SL;
}
__device__ __forceinline__ float sigm1(float x) {
    return 1.f / (1.f + expf(-x));
}

// Dot of one weight row (length 4*NITER, padded with zeros) against a
// row-pair activation vector stored as float2[k] = (row0, row1).
// 8 independent accumulator chains for FMA-latency hiding.
template<int NITER, bool STREAM>
__device__ __forceinline__ float2 dot_row(const float* __restrict__ Wrow,
                                          const float2* __restrict__ xin,
                                          float bias) {
    const float4* wr = reinterpret_cast<const float4*>(Wrow);
    const float4* xr = reinterpret_cast<const float4*>(xin);
    float a00 = bias, a01 = 0.f, a02 = 0.f, a03 = 0.f;
    float a10 = bias, a11 = 0.f, a12 = 0.f, a13 = 0.f;
#pragma unroll 4
    for (int i = 0; i < NITER; i++) {
        float4 w = STREAM ? __ldcs(wr + i) : __ldg(wr + i);
        float4 p = xr[2 * i];       // (x[4i].r0, x[4i].r1, x[4i+1].r0, x[4i+1].r1)
        float4 q = xr[2 * i + 1];   // (x[4i+2].r0, ...)
        a00 = fmaf(w.x, p.x, a00);  a10 = fmaf(w.x, p.y, a10);
        a01 = fmaf(w.y, p.z, a01);  a11 = fmaf(w.y, p.w, a11);
        a02 = fmaf(w.z, q.x, a02);  a12 = fmaf(w.z, q.y, a12);
        a03 = fmaf(w.w, q.z, a03);  a13 = fmaf(w.w, q.w, a13);
    }
    return make_float2((a00 + a01) + (a02 + a03), (a10 + a11) + (a12 + a13));
}

// Field MLP: s_in (101 used, padded zeros at 101..103, pad slot 275) -> s_f.
// Ping-pong: L1: s_in->s_hid, L2: s_hid->s_in, L3: s_in->s_f.
// Caller must __syncthreads() after building s_in. Returns synced.
__device__ __forceinline__ void field_eval(int tid,
        float2* s_in, float2* s_hid, float2* s_f,
        const float* __restrict__ fb1, const float* __restrict__ fb2,
        const float* __restrict__ fb3) {
    if (tid < HFF) {
        float2 a = dot_row<K1P / 4, false>(g_pW1 + tid * K1P, s_in, __ldg(fb1 + tid));
        s_hid[tid] = make_float2(tanhf(a.x), tanhf(a.y));
    }
    __syncthreads();
    if (tid < HFF) {
        float2 a = dot_row<K2P / 4, true>(g_pW2 + tid * K2P, s_hid, __ldg(fb2 + tid));
        s_in[tid] = make_float2(tanhf(a.x), tanhf(a.y));
    }
    __syncthreads();
    if (tid < HH) {
        float2 a = dot_row<K2P / 4, false>(g_pW3 + tid * K2P, s_in, __ldg(fb3 + tid));
        s_f[tid] = make_float2(tanhf(a.x), tanhf(a.y));
    }
    __syncthreads();
}

// RK4 with NSUB=2 substeps: y (s_y) advanced from t0 to t1 (per-row times).
__device__ __forceinline__ void integrate2(int tid, float2 t0, float2 t1,
        float2* s_in, float2* s_hid, float2* s_y, float2* s_ks, float2* s_f,
        const float* __restrict__ fb1, const float* __restrict__ fb2,
        const float* __restrict__ fb3) {
    float2 dt = make_float2((t1.x - t0.x) * 0.5f, (t1.y - t0.y) * 0.5f);
#pragma unroll 1
    for (int sub = 0; sub < 2; sub++) {
        float2 t  = make_float2(t0.x + (float)sub * dt.x, t0.y + (float)sub * dt.y);
        float2 th = make_float2(t.x + 0.5f * dt.x, t.y + 0.5f * dt.y);
        float2 te = make_float2(t.x + dt.x, t.y + dt.y);

        // stage 1: x = [t, y]
        if (tid < HH)        s_in[1 + tid] = s_y[tid];
        else if (tid < 103)  s_in[1 + tid] = make_float2(0.f, 0.f);
        if (tid == 0)        s_in[0] = t;
        __syncthreads();
        field_eval(tid, s_in, s_hid, s_f, fb1, fb2, fb3);            // k1
        if (tid < HH) {
            float2 f = s_f[tid], y = s_y[tid];
            s_ks[tid] = f;
            s_in[1 + tid] = make_float2(fmaf(0.5f * dt.x, f.x, y.x),
                                        fmaf(0.5f * dt.y, f.y, y.y));
        } else if (tid < 103) s_in[1 + tid] = make_float2(0.f, 0.f);
        if (tid == 0) s_in[0] = th;
        __syncthreads();
        field_eval(tid, s_in, s_hid, s_f, fb1, fb2, fb3);            // k2
        if (tid < HH) {
            float2 f = s_f[tid], y = s_y[tid], k = s_ks[tid];
            s_ks[tid] = make_float2(k.x + 2.f * f.x, k.y + 2.f * f.y);
            s_in[1 + tid] = make_float2(fmaf(0.5f * dt.x, f.x, y.x),
                                        fmaf(0.5f * dt.y, f.y, y.y));
        } else if (tid < 103) s_in[1 + tid] = make_float2(0.f, 0.f);
        if (tid == 0) s_in[0] = th;
        __syncthreads();
        field_eval(tid, s_in, s_hid, s_f, fb1, fb2, fb3);            // k3
        if (tid < HH) {
            float2 f = s_f[tid], y = s_y[tid], k = s_ks[tid];
            s_ks[tid] = make_float2(k.x + 2.f * f.x, k.y + 2.f * f.y);
            s_in[1 + tid] = make_float2(fmaf(dt.x, f.x, y.x),
                                        fmaf(dt.y, f.y, y.y));
        } else if (tid < 103) s_in[1 + tid] = make_float2(0.f, 0.f);
        if (tid == 0) s_in[0] = te;
        __syncthreads();
        field_eval(tid, s_in, s_hid, s_f, fb1, fb2, fb3);            // k4
        if (tid < HH) {
            float2 f = s_f[tid], y = s_y[tid], k = s_ks[tid];
            s_y[tid] = make_float2(y.x + dt.x * (k.x + f.x) / 6.f,
                                   y.y + dt.y * (k.y + f.y) / 6.f);
        }
        __syncthreads();
    }
}

// -------- prep: pad field weights to /4 strides, zero padding --------
__global__ void prep_kernel(const float* __restrict__ fW1,
                            const float* __restrict__ fW2,
                            const float* __restrict__ fW3) {
    int i = blockIdx.x * blockDim.x + threadIdx.x;
    if (i < HFF * K1P) {
        int n = i / K1P, k = i % K1P;
        g_pW1[i] = (k < K1) ? fW1[n * K1 + k] : 0.f;
    }
    int j = i - HFF * K1P;
    if (j >= 0 && j < HFF * K2P) {
        int n = j / K2P, k = j % K2P;
        g_pW2[j] = (k < HFF) ? fW2[n * HFF + k] : 0.f;
    }
    int l = i - HFF * K1P - HFF * K2P;
    if (l >= 0 && l < HH * K2P) {
        int n = l / K2P, k = l % K2P;
        g_pW3[l] = (k < HFF) ? fW3[n * HFF + k] : 0.f;
    }
}

// -------- encode: 32 steps of (ODE integrate + GRU) per row-pair --------
__global__ void __launch_bounds__(NTHR) encode_kernel(
        const float* __restrict__ past, const float* __restrict__ h0,
        const float* __restrict__ fb1, const float* __restrict__ fb2,
        const float* __restrict__ fb3,
        const float* __restrict__ Wih, const float* __restrict__ Whh,
        const float* __restrict__ bih, const float* __restrict__ bhh) {
    __shared__ __align__(16) float2 s_in[K2P];
    __shared__ __align__(16) float2 s_hid[K2P];
    __shared__ __align__(16) float2 s_y[HH];
    __shared__ float2 s_ks[HH], s_f[HH];
    __shared__ float2 s_u[200], s_inn[HH], s_hn[HH];

    int tid = threadIdx.x;
    int r0 = blockIdx.x * 2, r1 = r0 + 1;

    if (tid == 0) { s_in[K2P - 1] = make_float2(0.f, 0.f); s_hid[K2P - 1] = make_float2(0.f, 0.f); }
    if (tid < HH) s_y[tid] = make_float2(h0[r0 * HH + tid], h0[r1 * HH + tid]);
    __syncthreads();

    float2 tprev = make_float2(0.f, 0.f);
    for (int step = 0; step < TP; step++) {
        float2 tcur = make_float2(past[(r0 * TP + step) * 2], past[(r1 * TP + step) * 2]);
        float2 t0 = (step == 0) ? make_float2(tcur.x - 1.f, tcur.y - 1.f) : tprev;
        integrate2(tid, t0, tcur, s_in, s_hid, s_y, s_ks, s_f, fb1, fb2, fb3);

        // GRU (D = 1): gi[j] = Wih[j]*x + bih[j]; gh[j] = Whh[j]·h + bhh[j]
        float2 x = make_float2(past[(r0 * TP + step) * 2 + 1], past[(r1 * TP + step) * 2 + 1]);
        for (int jj = tid; jj < 3 * HH; jj += NTHR) {
            float wi = __ldg(Wih + jj);
            float bi = __ldg(bih + jj);
            float2 gi = make_float2(fmaf(wi, x.x, bi), fmaf(wi, x.y, bi));
            float2 a = dot_row<HH / 4, false>(Whh + jj * HH, s_y, __ldg(bhh + jj));
            if (jj < 2 * HH) s_u[jj] = make_float2(gi.x + a.x, gi.y + a.y);
            else { s_inn[jj - 2 * HH] = gi; s_hn[jj - 2 * HH] = a; }
        }
        __syncthreads();
        if (tid < HH) {
            float2 u1 = s_u[tid], u2 = s_u[HH + tid];
            float2 gin = s_inn[tid], ghn = s_hn[tid], h = s_y[tid];
            float rx = sigm1(u1.x), ry = sigm1(u1.y);
            float zx = sigm1(u2.x), zy = sigm1(u2.y);
            float nx = tanhf(gin.x + rx * ghn.x), ny = tanhf(gin.y + ry * ghn.y);
            s_y[tid] = make_float2((1.f - zx) * nx + zx * h.x,
                                   (1.f - zy) * ny + zy * h.y);
        }
        __syncthreads();
        tprev = tcur;
    }
    if (tid < HH) {
        g_hB[r0 * HH + tid] = s_y[tid].x;
        g_hB[r1 * HH + tid] = s_y[tid].y;
    }
}

// -------- decoder head: gx = MLP(h) per row --------
__global__ void gx_kernel(const float* __restrict__ gW1, const float* __restrict__ gb1,
                          const float* __restrict__ gW2, const float* __restrict__ gb2,
                          const float* __restrict__ gW3, const float* __restrict__ gb3) {
    int b = blockIdx.x, tid = threadIdx.x;
    __shared__ float sh[HH], s1[HGG], s2[HGG];
    for (int k = tid; k < HH; k += blockDim.x) sh[k] = g_hB[b * HH + k];
    __syncthreads();
    if (tid < HGG) {
        float a = __ldg(gb1 + tid);
        const float* w = gW1 + tid * HH;
        for (int k = 0; k < HH; k++) a = fmaf(__ldg(w + k), sh[k], a);
        s1[tid] = leaky1(a);
    }
    __syncthreads();
    if (tid < HGG) {
        float a = __ldg(gb2 + tid);
        const float* w = gW2 + tid * HGG;
        for (int k = 0; k < HGG; k++) a = fmaf(__ldg(w + k), s1[k], a);
        s2[tid] = leaky1(a);
    }
    __syncthreads();
    if (tid < 2) {
        float a = __ldg(gb3 + tid);
        const float* w = gW3 + tid * HGG;
        for (int k = 0; k < HGG; k++) a = fmaf(__ldg(w + k), s2[k], a);
        g_gx[b * 2 + tid] = a;
    }
}

// -------- z0: reparameterization with the concat/reshape shuffle --------
__global__ void z0_kernel(const float* __restrict__ eps) {
    int b = blockIdx.x, h = threadIdx.x;
    // v[j] = j<256 ? gx[j][0] : |gx[j-256][1]| ; loc[b]=v[2b], scale[b]=v[2b+1]
    float loc, scale;
    if (b < NB / 2) {
        loc   = g_gx[(2 * b) * 2 + 0];
        scale = g_gx[(2 * b + 1) * 2 + 0];
    } else {
        int i = 2 * (b - NB / 2);
        loc   = fabsf(g_gx[i * 2 + 1]);
        scale = fabsf(g_gx[(i + 1) * 2 + 1]);
    }
    g_z0[b * HH + h] = loc + scale * eps[h * NB + b];
}

// -------- rollout: 255 integrations + output MLP per step --------
__device__ __forceinline__ void out_mlp(int tid, int s, int r0, int r1,
        float2* s_in, float2* s_hid, const float2* s_y,
        const float* __restrict__ oW1, const float* __restrict__ ob1,
        const float* __restrict__ oW2, const float* __restrict__ ob2,
        const float* __restrict__ oW3, const float* __restrict__ ob3,
        float* __restrict__ out) {
    if (tid < HOO) {
        float2 a = dot_row<HH / 4, false>(oW1 + tid * HH, s_y, __ldg(ob1 + tid));
        s_hid[tid] = make_float2(leaky1(a.x), leaky1(a.y));
    }
    __syncthreads();
    if (tid < HOO) {
        float a0 = __ldg(ob2 + tid), a1 = a0;
        const float* w = oW2 + tid * HOO;
        for (int k = 0; k < HOO; k++) {
            float wv = __ldg(w + k);
            float2 h = s_hid[k];
            a0 = fmaf(wv, h.x, a0); a1 = fmaf(wv, h.y, a1);
        }
        s_in[tid] = make_float2(leaky1(a0), leaky1(a1));
    }
    __syncthreads();
    if (tid == 0) {
        float a0 = __ldg(ob3), a1 = a0;
        for (int k = 0; k < HOO; k++) {
            float wv = __ldg(oW3 + k);
            float2 h = s_in[k];
            a0 = fmaf(wv, h.x, a0); a1 = fmaf(wv, h.y, a1);
        }
        out[r0 * TFUT + s] = a0;
        out[r1 * TFUT + s] = a1;
    }
    __syncthreads();
}

__global__ void __launch_bounds__(NTHR) rollout_kernel(
        const float* __restrict__ tf_,
        const float* __restrict__ fb1, const float* __restrict__ fb2,
        const float* __restrict__ fb3,
        const float* __restrict__ oW1, const float* __restrict__ ob1,
        const float* __restrict__ oW2, const float* __restrict__ ob2,
        const float* __restrict__ oW3, const float* __restrict__ ob3,
        float* __restrict__ out) {
    __shared__ __align__(16) float2 s_in[K2P];
    __shared__ __align__(16) float2 s_hid[K2P];
    __shared__ __align__(16) float2 s_y[HH];
    __shared__ float2 s_ks[HH], s_f[HH];

    int tid = threadIdx.x;
    int r0 = blockIdx.x * 2, r1 = r0 + 1;

    if (tid == 0) { s_in[K2P - 1] = make_float2(0.f, 0.f); s_hid[K2P - 1] = make_float2(0.f, 0.f); }
    if (tid < HH) s_y[tid] = make_float2(g_z0[r0 * HH + tid], g_z0[r1 * HH + tid]);
    __syncthreads();

    // t = 0 output (z0 itself)
    out_mlp(tid, 0, r0, r1, s_in, s_hid, s_y, oW1, ob1, oW2, ob2, oW3, ob3, out);

    float2 tprev = make_float2(tf_[r0 * TFUT], tf_[r1 * TFUT]);
    for (int s = 1; s < TFUT; s++) {
        float2 tcur = make_float2(tf_[r0 * TFUT + s], tf_[r1 * TFUT + s]);
        integrate2(tid, tprev, tcur, s_in, s_hid, s_y, s_ks, s_f, fb1, fb2, fb3);
        out_mlp(tid, s, r0, r1, s_in, s_hid, s_y, oW1, ob1, oW2, ob2, oW3, ob3, out);
        tprev = tcur;
    }
}

extern "C" void kernel_launch(void* const* d_in, const int* in_sizes, int n_in,
                              void* d_out, int out_size) {
    const float* past = (const float*)d_in[0];
    const float* h0   = (const float*)d_in[1];
    const float* t_fu = (const float*)d_in[2];
    const float* eps  = (const float*)d_in[3];
    const float* fW1  = (const float*)d_in[4];
    const float* fb1  = (const float*)d_in[5];
    const float* fW2  = (const float*)d_in[6];
    const float* fb2  = (const float*)d_in[7];
    const float* fW3  = (const float*)d_in[8];
    const float* fb3  = (const float*)d_in[9];
    const float* Wih  = (const float*)d_in[10];
    const float* Whh  = (const float*)d_in[11];
    const float* bih  = (const float*)d_in[12];
    const float* bhh  = (const float*)d_in[13];
    const float* gW1  = (const float*)d_in[14];
    const float* gb1  = (const float*)d_in[15];
    const float* gW2  = (const float*)d_in[16];
    const float* gb2  = (const float*)d_in[17];
    const float* gW3  = (const float*)d_in[18];
    const float* gb3  = (const float*)d_in[19];
    const float* oW1  = (const float*)d_in[20];
    const float* ob1  = (const float*)d_in[21];
    const float* oW2  = (const float*)d_in[22];
    const float* ob2  = (const float*)d_in[23];
    const float* oW3  = (const float*)d_in[24];
    const float* ob3  = (const float*)d_in[25];
    float* out = (float*)d_out;

    const int prep_total = HFF * K1P + HFF * K2P + HH * K2P;
    prep_kernel<<<(prep_total + 255) / 256, 256>>>(fW1, fW2, fW3);
    encode_kernel<<<NCTA, NTHR>>>(past, h0, fb1, fb2, fb3, Wih, Whh, bih, bhh);
    gx_kernel<<<NB, 96>>>(gW1, gb1, gW2, gb2, gW3, gb3);
    z0_kernel<<<NB, HH>>>(eps);
    rollout_kernel<<<NCTA, NTHR>>>(t_fu, fb1, fb2, fb3,
                                   oW1, ob1, oW2, ob2, oW3, ob3, out);
}

// round 7
// speedup vs baseline: 1.5086x; 1.5076x over previous
#include <cuda_runtime.h>
#include <math.h>

#define NB    256
#define TP    32
#define TFUT  256
#define HH    100
#define NF    275
#define HGG   75
#define HOO   75
#define NTHR  288
#define NCTA  128

// ---- transposed weights in global scratch ----
__device__ __align__(16) float g_W13T[55276];      // [0,27775) W1T[k*275+n]; 27775 pad; [27776,+27500) W3T[k*100+n]
__device__ __align__(16) float g_W2T[275 * 276];   // W2T[k*276+n], col 275 = 0
__device__ __align__(16) float g_WhhT[100 * 300];  // WhhT[k*300+j]
__device__ __align__(16) float g_oW1T[100 * 75];
__device__ __align__(16) float g_oW2T[75 * 75];
__device__ float g_hB[NB * HH];
__device__ float g_gx[NB * 2];
__device__ float g_z0[NB * HH];

// ---- shared layout (float offsets), total 57736 floats = 230,944 B ----
#define OFF_W1T  0
#define OFF_W3T  27776
#define OFF_IN   55276   // float2[101]
#define OFF_HID  55480   // float2[276]
#define OFF_A2   56032   // float2[276]
#define OFF_Y    56584   // float2[100]
#define OFF_KS   56784   // float2[100]
#define OFF_F    56984   // float2[100]
#define OFF_PART 57184   // float4[138]
#define SMEM_BYTES (57736 * 4)

__device__ __forceinline__ float leaky1(float x) {
    const float SL = 1.0f / 5.5f;
    return x >= 0.f ? x : x * SL;
}
__device__ __forceinline__ float sigm1(float x) { return 1.f / (1.f + expf(-x)); }

// Layer-2 partial: outputs (n0, n0+1), k in [K0,K1). Coalesced LDG.64 from W2T.
template<int K0, int K1>
__device__ __forceinline__ float4 dotW2(const float* __restrict__ W2T,
                                        const float* __restrict__ smx, int n0) {
    float a00 = 0.f, a01 = 0.f, a10 = 0.f, a11 = 0.f;
    float b00 = 0.f, b01 = 0.f, b10 = 0.f, b11 = 0.f;
    const float4* x4 = (const float4*)smx;
#pragma unroll 4
    for (int k = K0; k + 1 < K1; k += 2) {
        float2 w0 = __ldcg((const float2*)(W2T + k * 276 + n0));
        float2 w1 = __ldcg((const float2*)(W2T + (k + 1) * 276 + n0));
        float4 x = x4[k >> 1];
        a00 = fmaf(w0.x, x.x, a00); a01 = fmaf(w0.x, x.y, a01);
        a10 = fmaf(w0.y, x.x, a10); a11 = fmaf(w0.y, x.y, a11);
        b00 = fmaf(w1.x, x.z, b00); b01 = fmaf(w1.x, x.w, b01);
        b10 = fmaf(w1.y, x.z, b10); b11 = fmaf(w1.y, x.w, b11);
    }
    if ((K1 - K0) & 1) {
        float2 w0 = __ldcg((const float2*)(W2T + (K1 - 1) * 276 + n0));
        float2 x = ((const float2*)smx)[K1 - 1];
        a00 = fmaf(w0.x, x.x, a00); a01 = fmaf(w0.x, x.y, a01);
        a10 = fmaf(w0.y, x.x, a10); a11 = fmaf(w0.y, x.y, a11);
    }
    return make_float4(a00 + b00, a01 + b01, a10 + b10, a11 + b11);
}

// Layer-3 partial: output n, k in [K0,K1). W3T in SMEM, lane-coalesced LDS.
template<int K0, int K1>
__device__ __forceinline__ float2 dotW3(const float* __restrict__ smW3,
                                        const float* __restrict__ smx, int n) {
    float a0 = 0.f, a1 = 0.f, b0 = 0.f, b1 = 0.f;
    const float4* x4 = (const float4*)smx;
#pragma unroll 4
    for (int k = K0; k + 1 < K1; k += 2) {
        float w0 = smW3[k * 100 + n], w1 = smW3[(k + 1) * 100 + n];
        float4 x = x4[k >> 1];
        a0 = fmaf(w0, x.x, a0); a1 = fmaf(w0, x.y, a1);
        b0 = fmaf(w1, x.z, b0); b1 = fmaf(w1, x.w, b1);
    }
    if ((K1 - K0) & 1) {
        float w = smW3[(K1 - 1) * 100 + n];
        float2 x = ((const float2*)smx)[K1 - 1];
        a0 = fmaf(w, x.x, a0); a1 = fmaf(w, x.y, a1);
    }
    return make_float2(a0 + b0, a1 + b1);
}

// Field MLP on a row pair. Input s_in (float2[101]) -> s_f (float2[100]). Ends synced.
__device__ __forceinline__ void field_eval2(int tid, float* sm,
        float rb1, float rb2a, float rb2b, float rb3) {
    float2* s_hid = (float2*)(sm + OFF_HID);
    float2* s_a2  = (float2*)(sm + OFF_A2);
    float2* s_f   = (float2*)(sm + OFF_F);
    float4* s_p4  = (float4*)(sm + OFF_PART);
    float2* s_p2  = (float2*)(sm + OFF_PART);

    // L1: 101 -> 275 (W1T in smem, lane-coalesced)
    if (tid < NF) {
        const float* w = sm + OFF_W1T + tid;
        const float4* x4 = (const float4*)(sm + OFF_IN);
        float a0 = rb1, a1 = rb1, b0 = 0.f, b1 = 0.f;
#pragma unroll 5
        for (int k = 0; k < 100; k += 2) {
            float w0 = w[k * 275], w1 = w[(k + 1) * 275];
            float4 x = x4[k >> 1];
            a0 = fmaf(w0, x.x, a0); a1 = fmaf(w0, x.y, a1);
            b0 = fmaf(w1, x.z, b0); b1 = fmaf(w1, x.w, b1);
        }
        float wl = w[100 * 275];
        float2 xl = ((const float2*)(sm + OFF_IN))[100];
        a0 = fmaf(wl, xl.x, a0); a1 = fmaf(wl, xl.y, a1);
        s_hid[tid] = make_float2(tanhf(a0 + b0), tanhf(a1 + b1));
    }
    __syncthreads();

    // L2: 275 -> 275 (W2T global, coalesced, k-split over 2 groups of 138 threads)
    int g = tid / 144, j = tid - g * 144;
    bool act = (j < 138);
    int n0 = 2 * j;
    float4 acc = make_float4(0.f, 0.f, 0.f, 0.f);
    if (act) {
        acc = (g == 0) ? dotW2<0, 138>(g_W2T, sm + OFF_HID, n0)
                       : dotW2<138, 275>(g_W2T, sm + OFF_HID, n0);
        if (g == 1) s_p4[j] = acc;
    }
    __syncthreads();
    if (act && g == 0) {
        float4 p = s_p4[j];
        s_a2[n0]     = make_float2(tanhf(acc.x + p.x + rb2a), tanhf(acc.y + p.y + rb2a));
        s_a2[n0 + 1] = make_float2(tanhf(acc.z + p.z + rb2b), tanhf(acc.w + p.w + rb2b));
    }
    __syncthreads();

    // L3: 275 -> 100 (W3T in smem, k-split over 2 groups of 100 threads)
    float2 a3 = make_float2(0.f, 0.f);
    if (tid < 100) {
        a3 = dotW3<0, 138>(sm + OFF_W3T, sm + OFF_A2, tid);
    } else if (tid < 200) {
        s_p2[tid - 100] = dotW3<138, 275>(sm + OFF_W3T, sm + OFF_A2, tid - 100);
    }
    __syncthreads();
    if (tid < 100) {
        float2 p = s_p2[tid];
        s_f[tid] = make_float2(tanhf(a3.x + p.x + rb3), tanhf(a3.y + p.y + rb3));
    }
    __syncthreads();
}

// RK4, NSUB=2, on row-pair state s_y.
__device__ __forceinline__ void integrate2(int tid, float* sm, float2 t0, float2 t1,
        float rb1, float rb2a, float rb2b, float rb3) {
    float2* s_in = (float2*)(sm + OFF_IN);
    float2* s_y  = (float2*)(sm + OFF_Y);
    float2* s_ks = (float2*)(sm + OFF_KS);
    float2* s_f  = (float2*)(sm + OFF_F);
    float2 dt = make_float2((t1.x - t0.x) * 0.5f, (t1.y - t0.y) * 0.5f);
#pragma unroll 1
    for (int sub = 0; sub < 2; sub++) {
        float2 t  = make_float2(t0.x + (float)sub * dt.x, t0.y + (float)sub * dt.y);
        float2 th = make_float2(t.x + 0.5f * dt.x, t.y + 0.5f * dt.y);
        float2 te = make_float2(t.x + dt.x, t.y + dt.y);

        if (tid < HH) s_in[1 + tid] = s_y[tid];
        if (tid == 0) s_in[0] = t;
        __syncthreads();
        field_eval2(tid, sm, rb1, rb2a, rb2b, rb3);               // k1
        if (tid < HH) {
            float2 f = s_f[tid], y = s_y[tid];
            s_ks[tid] = f;
            s_in[1 + tid] = make_float2(fmaf(0.5f * dt.x, f.x, y.x),
                                        fmaf(0.5f * dt.y, f.y, y.y));
        }
        if (tid == 0) s_in[0] = th;
        __syncthreads();
        field_eval2(tid, sm, rb1, rb2a, rb2b, rb3);               // k2
        if (tid < HH) {
            float2 f = s_f[tid], y = s_y[tid], k = s_ks[tid];
            s_ks[tid] = make_float2(k.x + 2.f * f.x, k.y + 2.f * f.y);
            s_in[1 + tid] = make_float2(fmaf(0.5f * dt.x, f.x, y.x),
                                        fmaf(0.5f * dt.y, f.y, y.y));
        }
        if (tid == 0) s_in[0] = th;
        __syncthreads();
        field_eval2(tid, sm, rb1, rb2a, rb2b, rb3);               // k3
        if (tid < HH) {
            float2 f = s_f[tid], y = s_y[tid], k = s_ks[tid];
            s_ks[tid] = make_float2(k.x + 2.f * f.x, k.y + 2.f * f.y);
            s_in[1 + tid] = make_float2(fmaf(dt.x, f.x, y.x),
                                        fmaf(dt.y, f.y, y.y));
        }
        if (tid == 0) s_in[0] = te;
        __syncthreads();
        field_eval2(tid, sm, rb1, rb2a, rb2b, rb3);               // k4
        if (tid < HH) {
            float2 f = s_f[tid], y = s_y[tid], k = s_ks[tid];
            s_y[tid] = make_float2(y.x + dt.x * (k.x + f.x) / 6.f,
                                   y.y + dt.y * (k.y + f.y) / 6.f);
        }
        __syncthreads();
    }
}

// ---- prep: build all transposed weight copies ----
__global__ void prep_kernel(const float* __restrict__ fW1, const float* __restrict__ fW2,
                            const float* __restrict__ fW3, const float* __restrict__ Whh,
                            const float* __restrict__ oW1, const float* __restrict__ oW2) {
    for (int i = blockIdx.x * blockDim.x + threadIdx.x; i < 174301;
         i += gridDim.x * blockDim.x) {
        if (i < 55276) {
            if (i < 27775) {
                int k = i / 275, n = i % 275;
                g_W13T[i] = fW1[n * 101 + k];
            } else if (i == 27775) {
                g_W13T[i] = 0.f;
            } else {
                int j = i - 27776, k = j / 100, n = j % 100;
                g_W13T[i] = fW3[n * 275 + k];
            }
        } else if (i < 55276 + 75900) {
            int j = i - 55276, k = j / 276, n = j % 276;
            g_W2T[j] = (n < 275) ? fW2[n * 275 + k] : 0.f;
        } else if (i < 55276 + 75900 + 30000) {
            int j = i - 131176, k = j / 300, n = j % 300;
            g_WhhT[j] = Whh[n * 100 + k];
        } else if (i < 161176 + 7500) {
            int j = i - 161176, k = j / 75, n = j % 75;
            g_oW1T[j] = oW1[n * 100 + k];
        } else {
            int j = i - 168676, k = j / 75, n = j % 75;
            g_oW2T[j] = oW2[n * 75 + k];
        }
    }
}

// ---- encode ----
__global__ void __launch_bounds__(NTHR, 1) encode_kernel(
        const float* __restrict__ past, const float* __restrict__ h0,
        const float* __restrict__ fb1, const float* __restrict__ fb2,
        const float* __restrict__ fb3,
        const float* __restrict__ Wih, const float* __restrict__ bih,
        const float* __restrict__ bhh) {
    extern __shared__ float sm[];
    int tid = threadIdx.x;
    int r0 = blockIdx.x * 2, r1 = r0 + 1;

    const float4* src = (const float4*)g_W13T;
    float4* dst = (float4*)sm;
    for (int i = tid; i < 55276 / 4; i += NTHR) dst[i] = src[i];

    float rb1 = (tid < NF) ? __ldg(fb1 + tid) : 0.f;
    int g = tid / 144, j = tid - g * 144;
    float rb2a = 0.f, rb2b = 0.f;
    if (g == 0 && j < 138) {
        rb2a = __ldg(fb2 + 2 * j);
        rb2b = (2 * j + 1 < NF) ? __ldg(fb2 + 2 * j + 1) : 0.f;
    }
    float rb3 = (tid < HH) ? __ldg(fb3 + tid) : 0.f;

    float2* s_y = (float2*)(sm + OFF_Y);
    float2* s_u   = (float2*)(sm + OFF_HID);   // [200]  aliased
    float2* s_inn = (float2*)(sm + OFF_A2);    // [100]
    float2* s_hn  = (float2*)(sm + OFF_PART);  // [100]
    if (tid < HH) s_y[tid] = make_float2(h0[r0 * HH + tid], h0[r1 * HH + tid]);
    __syncthreads();

    float2 tprev = make_float2(0.f, 0.f);
    for (int step = 0; step < TP; step++) {
        float2 tcur = make_float2(past[(r0 * TP + step) * 2], past[(r1 * TP + step) * 2]);
        float2 t0 = (step == 0) ? make_float2(tcur.x - 1.f, tcur.y - 1.f) : tprev;
        integrate2(tid, sm, t0, tcur, rb1, rb2a, rb2b, rb3);

        float2 x = make_float2(past[(r0 * TP + step) * 2 + 1],
                               past[(r1 * TP + step) * 2 + 1]);
        const float4* y4 = (const float4*)(sm + OFF_Y);
        for (int jj = tid; jj < 300; jj += NTHR) {
            float bh = __ldg(bhh + jj);
            float a0 = bh, a1 = bh, b0 = 0.f, b1 = 0.f;
#pragma unroll 5
            for (int k = 0; k < 100; k += 2) {
                float w0 = __ldcg(g_WhhT + k * 300 + jj);
                float w1 = __ldcg(g_WhhT + (k + 1) * 300 + jj);
                float4 y = y4[k >> 1];
                a0 = fmaf(w0, y.x, a0); a1 = fmaf(w0, y.y, a1);
                b0 = fmaf(w1, y.z, b0); b1 = fmaf(w1, y.w, b1);
            }
            a0 += b0; a1 += b1;
            float wi = __ldg(Wih + jj), bi = __ldg(bih + jj);
            float2 gi = make_float2(fmaf(wi, x.x, bi), fmaf(wi, x.y, bi));
            if (jj < 200) s_u[jj] = make_float2(gi.x + a0, gi.y + a1);
            else { s_inn[jj - 200] = gi; s_hn[jj - 200] = make_float2(a0, a1); }
        }
        __syncthreads();
        if (tid < HH) {
            float2 u1 = s_u[tid], u2 = s_u[HH + tid];
            float2 gin = s_inn[tid], ghn = s_hn[tid], h = s_y[tid];
            float rx = sigm1(u1.x), ry = sigm1(u1.y);
            float zx = sigm1(u2.x), zy = sigm1(u2.y);
            float nx = tanhf(gin.x + rx * ghn.x), ny = tanhf(gin.y + ry * ghn.y);
            s_y[tid] = make_float2((1.f - zx) * nx + zx * h.x,
                                   (1.f - zy) * ny + zy * h.y);
        }
        __syncthreads();
        tprev = tcur;
    }
    if (tid < HH) {
        g_hB[r0 * HH + tid] = s_y[tid].x;
        g_hB[r1 * HH + tid] = s_y[tid].y;
    }
}

// ---- decoder head ----
__global__ void gx_kernel(const float* __restrict__ gW1, const float* __restrict__ gb1,
                          const float* __restrict__ gW2, const float* __restrict__ gb2,
                          const float* __restrict__ gW3, const float* __restrict__ gb3) {
    int b = blockIdx.x, tid = threadIdx.x;
    __shared__ float sh[HH], s1[HGG], s2[HGG];
    for (int k = tid; k < HH; k += blockDim.x) sh[k] = g_hB[b * HH + k];
    __syncthreads();
    if (tid < HGG) {
        float a = __ldg(gb1 + tid);
        const float* w = gW1 + tid * HH;
        for (int k = 0; k < HH; k++) a = fmaf(__ldg(w + k), sh[k], a);
        s1[tid] = leaky1(a);
    }
    __syncthreads();
    if (tid < HGG) {
        float a = __ldg(gb2 + tid);
        const float* w = gW2 + tid * HGG;
        for (int k = 0; k < HGG; k++) a = fmaf(__ldg(w + k), s1[k], a);
        s2[tid] = leaky1(a);
    }
    __syncthreads();
    if (tid < 2) {
        float a = __ldg(gb3 + tid);
        const float* w = gW3 + tid * HGG;
        for (int k = 0; k < HGG; k++) a = fmaf(__ldg(w + k), s2[k], a);
        g_gx[b * 2 + tid] = a;
    }
}

__global__ void z0_kernel(const float* __restrict__ eps) {
    int b = blockIdx.x, h = threadIdx.x;
    float loc, scale;
    if (b < NB / 2) {
        loc   = g_gx[(2 * b) * 2 + 0];
        scale = g_gx[(2 * b + 1) * 2 + 0];
    } else {
        int i = 2 * (b - NB / 2);
        loc   = fabsf(g_gx[i * 2 + 1]);
        scale = fabsf(g_gx[(i + 1) * 2 + 1]);
    }
    g_z0[b * HH + h] = loc + scale * eps[h * NB + b];
}

// ---- rollout ----
__device__ __forceinline__ void out_mlp(int tid, int s, int r0, int r1, float* sm,
        float rob1, float rob2,
        const float* __restrict__ oW3, const float* __restrict__ ob3,
        float* __restrict__ out) {
    float2* s_o1 = (float2*)(sm + OFF_HID);
    float2* s_o2 = (float2*)(sm + OFF_A2);
    if (tid < HOO) {
        const float4* y4 = (const float4*)(sm + OFF_Y);
        float a0 = rob1, a1 = rob1, b0 = 0.f, b1 = 0.f;
#pragma unroll 5
        for (int k = 0; k < 100; k += 2) {
            float w0 = __ldcg(g_oW1T + k * 75 + tid);
            float w1 = __ldcg(g_oW1T + (k + 1) * 75 + tid);
            float4 y = y4[k >> 1];
            a0 = fmaf(w0, y.x, a0); a1 = fmaf(w0, y.y, a1);
            b0 = fmaf(w1, y.z, b0); b1 = fmaf(w1, y.w, b1);
        }
        s_o1[tid] = make_float2(leaky1(a0 + b0), leaky1(a1 + b1));
    }
    __syncthreads();
    if (tid < HOO) {
        const float4* h4 = (const float4*)(sm + OFF_HID);
        float a0 = rob2, a1 = rob2, b0 = 0.f, b1 = 0.f;
#pragma unroll 4
        for (int k = 0; k + 1 < HOO; k += 2) {
            float w0 = __ldcg(g_oW2T + k * 75 + tid);
            float w1 = __ldcg(g_oW2T + (k + 1) * 75 + tid);
            float4 h = h4[k >> 1];
            a0 = fmaf(w0, h.x, a0); a1 = fmaf(w0, h.y, a1);
            b0 = fmaf(w1, h.z, b0); b1 = fmaf(w1, h.w, b1);
        }
        {   // tail k = 74
            float w0 = __ldcg(g_oW2T + 74 * 75 + tid);
            float2 h = s_o1[74];
            a0 = fmaf(w0, h.x, a0); a1 = fmaf(w0, h.y, a1);
        }
        s_o2[tid] = make_float2(leaky1(a0 + b0), leaky1(a1 + b1));
    }
    __syncthreads();
    if (tid < 32) {
        float a0 = 0.f, a1 = 0.f;
        for (int k = tid; k < HOO; k += 32) {
            float wv = __ldg(oW3 + k);
            float2 h = s_o2[k];
            a0 = fmaf(wv, h.x, a0); a1 = fmaf(wv, h.y, a1);
        }
#pragma unroll
        for (int o = 16; o; o >>= 1) {
            a0 += __shfl_down_sync(0xffffffffu, a0, o);
            a1 += __shfl_down_sync(0xffffffffu, a1, o);
        }
        if (tid == 0) {
            float b = __ldg(ob3);
            out[r0 * TFUT + s] = a0 + b;
            out[r1 * TFUT + s] = a1 + b;
        }
    }
    __syncthreads();
}

__global__ void __launch_bounds__(NTHR, 1) rollout_kernel(
        const float* __restrict__ tf_,
        const float* __restrict__ fb1, const float* __restrict__ fb2,
        const float* __restrict__ fb3,
        const float* __restrict__ ob1, const float* __restrict__ ob2,
        const float* __restrict__ oW3, const float* __restrict__ ob3,
        float* __restrict__ out) {
    extern __shared__ float sm[];
    int tid = threadIdx.x;
    int r0 = blockIdx.x * 2, r1 = r0 + 1;

    const float4* src = (const float4*)g_W13T;
    float4* dst = (float4*)sm;
    for (int i = tid; i < 55276 / 4; i += NTHR) dst[i] = src[i];

    float rb1 = (tid < NF) ? __ldg(fb1 + tid) : 0.f;
    int g = tid / 144, j = tid - g * 144;
    float rb2a = 0.f, rb2b = 0.f;
    if (g == 0 && j < 138) {
        rb2a = __ldg(fb2 + 2 * j);
        rb2b = (2 * j + 1 < NF) ? __ldg(fb2 + 2 * j + 1) : 0.f;
    }
    float rb3 = (tid < HH) ? __ldg(fb3 + tid) : 0.f;
    float rob1 = (tid < HOO) ? __ldg(ob1 + tid) : 0.f;
    float rob2 = (tid < HOO) ? __ldg(ob2 + tid) : 0.f;

    float2* s_y = (float2*)(sm + OFF_Y);
    if (tid < HH) s_y[tid] = make_float2(g_z0[r0 * HH + tid], g_z0[r1 * HH + tid]);
    __syncthreads();

    out_mlp(tid, 0, r0, r1, sm, rob1, rob2, oW3, ob3, out);

    float2 tprev = make_float2(tf_[r0 * TFUT], tf_[r1 * TFUT]);
    for (int s = 1; s < TFUT; s++) {
        float2 tcur = make_float2(tf_[r0 * TFUT + s], tf_[r1 * TFUT + s]);
        integrate2(tid, sm, tprev, tcur, rb1, rb2a, rb2b, rb3);
        out_mlp(tid, s, r0, r1, sm, rob1, rob2, oW3, ob3, out);
        tprev = tcur;
    }
}

extern "C" void kernel_launch(void* const* d_in, const int* in_sizes, int n_in,
                              void* d_out, int out_size) {
    const float* past = (const float*)d_in[0];
    const float* h0   = (const float*)d_in[1];
    const float* t_fu = (const float*)d_in[2];
    const float* eps  = (const float*)d_in[3];
    const float* fW1  = (const float*)d_in[4];
    const float* fb1  = (const float*)d_in[5];
    const float* fW2  = (const float*)d_in[6];
    const float* fb2  = (const float*)d_in[7];
    const float* fW3  = (const float*)d_in[8];
    const float* fb3  = (const float*)d_in[9];
    const float* Wih  = (const float*)d_in[10];
    const float* Whh  = (const float*)d_in[11];
    const float* bih  = (const float*)d_in[12];
    const float* bhh  = (const float*)d_in[13];
    const float* gW1  = (const float*)d_in[14];
    const float* gb1  = (const float*)d_in[15];
    const float* gW2  = (const float*)d_in[16];
    const float* gb2  = (const float*)d_in[17];
    const float* gW3  = (const float*)d_in[18];
    const float* gb3  = (const float*)d_in[19];
    const float* oW1  = (const float*)d_in[20];
    const float* ob1  = (const float*)d_in[21];
    const float* oW2  = (const float*)d_in[22];
    const float* ob2  = (const float*)d_in[23];
    const float* oW3  = (const float*)d_in[24];
    const float* ob3  = (const float*)d_in[25];
    float* out = (float*)d_out;

    static bool attr_done = false;
    if (!attr_done) {
        cudaFuncSetAttribute(encode_kernel,
                             cudaFuncAttributeMaxDynamicSharedMemorySize, SMEM_BYTES);
        cudaFuncSetAttribute(rollout_kernel,
                             cudaFuncAttributeMaxDynamicSharedMemorySize, SMEM_BYTES);
        attr_done = true;
    }

    prep_kernel<<<192, 256>>>(fW1, fW2, fW3, Whh, oW1, oW2);
    encode_kernel<<<NCTA, NTHR, SMEM_BYTES>>>(past, h0, fb1, fb2, fb3, Wih, bih, bhh);
    gx_kernel<<<NB, 96>>>(gW1, gb1, gW2, gb2, gW3, gb3);
    z0_kernel<<<NB, HH>>>(eps);
    rollout_kernel<<<NCTA, NTHR, SMEM_BYTES>>>(t_fu, fb1, fb2, fb3,
                                               ob1, ob2, oW3, ob3, out);
}

// round 8
// speedup vs baseline: 2.7115x; 1.7974x over previous
#include <cuda_runtime.h>
#include <math.h>

#define NB    256
#define TP    32
#define TFUT  256
#define HH    100
#define NF    275
#define HGG   75
#define HOO   75
#define NTHR  288
#define NCTA  128

// ---- transposed weights in global scratch ----
// g_W13T: [0,27775) W1T[k*275+n]; [27775] pad; [27776,55376) W3T[k*100+n] (276 rows, row 275 = 0)
__device__ __align__(16) float g_W13T[55376];
__device__ __align__(16) float g_W2T[276 * 276];   // W2T[k*276+n]; col 275 = 0, row 275 = 0
__device__ __align__(16) float g_WhhT[100 * 300];
__device__ __align__(16) float g_oW1T[100 * 75];
__device__ __align__(16) float g_oW2T[75 * 75];
__device__ float g_hB[NB * HH];
__device__ float g_gx[NB * 2];
__device__ float g_z0[NB * HH];

// ---- shared layout (float offsets), total 57636 floats = 230,544 B ----
#define OFF_W1T  0        // 27775 + 1 pad
#define OFF_W3T  27776    // 276*100 = 27600
#define OFF_IN   55376    // float2[101] = 202 + 2 pad
#define OFF_HID  55580    // float2[276]
#define OFF_A2   56132    // float2[276]
#define OFF_Y    56684    // float2[100]
#define OFF_KS   56884    // float2[100]
#define OFF_PART 57084    // float4[138]
#define SMEM_BYTES (57636 * 4)

__device__ __forceinline__ float leaky1(float x) {
    const float SL = 1.0f / 5.5f;
    return x >= 0.f ? x : x * SL;
}
__device__ __forceinline__ float sigm1(float x) { return 1.f / (1.f + expf(-x)); }

// ---- Layer-2 partial: outputs (n0,n0+1) for both rows, NK=138 k's. ----
// Double-buffered 16-deep LDG.64 pipeline + tail prefetched up front.
__device__ __forceinline__ float4 dotW2(const float* __restrict__ p,
                                        const float2* __restrict__ x2) {
    float a00 = 0.f, a01 = 0.f, a10 = 0.f, a11 = 0.f;
    float b00 = 0.f, b01 = 0.f, b10 = 0.f, b11 = 0.f;
    float2 w[16], wn[16], wt[10];
#pragma unroll
    for (int i = 0; i < 16; i++) w[i] = __ldcg((const float2*)(p + i * 276));
#pragma unroll
    for (int i = 0; i < 10; i++) wt[i] = __ldcg((const float2*)(p + (128 + i) * 276));
#pragma unroll
    for (int c = 0; c < 8; c++) {
        if (c < 7) {
#pragma unroll
            for (int i = 0; i < 16; i++)
                wn[i] = __ldcg((const float2*)(p + ((c + 1) * 16 + i) * 276));
        }
#pragma unroll
        for (int i = 0; i < 16; i += 2) {
            float2 x0 = x2[c * 16 + i], x1 = x2[c * 16 + i + 1];
            a00 = fmaf(w[i].x,     x0.x, a00); a01 = fmaf(w[i].x,     x0.y, a01);
            a10 = fmaf(w[i].y,     x0.x, a10); a11 = fmaf(w[i].y,     x0.y, a11);
            b00 = fmaf(w[i + 1].x, x1.x, b00); b01 = fmaf(w[i + 1].x, x1.y, b01);
            b10 = fmaf(w[i + 1].y, x1.x, b10); b11 = fmaf(w[i + 1].y, x1.y, b11);
        }
        if (c < 7) {
#pragma unroll
            for (int i = 0; i < 16; i++) w[i] = wn[i];
        }
    }
#pragma unroll
    for (int i = 0; i < 10; i++) {
        float2 x0 = x2[128 + i];
        a00 = fmaf(wt[i].x, x0.x, a00); a01 = fmaf(wt[i].x, x0.y, a01);
        a10 = fmaf(wt[i].y, x0.x, a10); a11 = fmaf(wt[i].y, x0.y, a11);
    }
    return make_float4(a00 + b00, a01 + b01, a10 + b10, a11 + b11);
}

// ---- Layer-3 partial: output n, NK=138, W3T in SMEM (stride 100, lane-coalesced). ----
__device__ __forceinline__ float2 dotW3(const float* __restrict__ w,
                                        const float2* __restrict__ x2) {
    float a0 = 0.f, a1 = 0.f, b0 = 0.f, b1 = 0.f;
#pragma unroll
    for (int c = 0; c < 17; c++) {
        float wr[8]; float2 xr[8];
#pragma unroll
        for (int i = 0; i < 8; i++) { wr[i] = w[(c * 8 + i) * 100]; xr[i] = x2[c * 8 + i]; }
#pragma unroll
        for (int i = 0; i < 8; i += 2) {
            a0 = fmaf(wr[i],     xr[i].x,     a0); a1 = fmaf(wr[i],     xr[i].y,     a1);
            b0 = fmaf(wr[i + 1], xr[i + 1].x, b0); b1 = fmaf(wr[i + 1], xr[i + 1].y, b1);
        }
    }
#pragma unroll
    for (int i = 136; i < 138; i++) {
        float wv = w[i * 100]; float2 x = x2[i];
        a0 = fmaf(wv, x.x, a0); a1 = fmaf(wv, x.y, a1);
    }
    return make_float2(a0 + b0, a1 + b1);
}

// ---- One RK4 stage: field MLP on s_in, fused stage update. Ends synced. ----
__device__ __forceinline__ void field_stage(int tid, float* sm, int stage,
        float2 dt, float2 tnext, bool write_in,
        float rb1, float rb2a, float rb2b, float rb3) {
    float2* s_in  = (float2*)(sm + OFF_IN);
    float2* s_hid = (float2*)(sm + OFF_HID);
    float2* s_a2  = (float2*)(sm + OFF_A2);
    float2* s_y   = (float2*)(sm + OFF_Y);
    float2* s_ks  = (float2*)(sm + OFF_KS);
    float4* s_p4  = (float4*)(sm + OFF_PART);
    float2* s_p2  = (float2*)(sm + OFF_PART);

    // L1: 101 -> 275 (W1T in smem)
    if (tid < NF) {
        const float* w = sm + OFF_W1T + tid;
        const float2* x2 = (const float2*)(sm + OFF_IN);
        float a0 = rb1, a1 = rb1, b0 = 0.f, b1 = 0.f, c0 = 0.f, c1 = 0.f, d0 = 0.f, d1 = 0.f;
#pragma unroll
        for (int c = 0; c < 12; c++) {
            float wr[8]; float2 xr[8];
#pragma unroll
            for (int i = 0; i < 8; i++) { wr[i] = w[(c * 8 + i) * 275]; xr[i] = x2[c * 8 + i]; }
#pragma unroll
            for (int i = 0; i < 8; i += 4) {
                a0 = fmaf(wr[i],     xr[i].x,     a0); a1 = fmaf(wr[i],     xr[i].y,     a1);
                b0 = fmaf(wr[i + 1], xr[i + 1].x, b0); b1 = fmaf(wr[i + 1], xr[i + 1].y, b1);
                c0 = fmaf(wr[i + 2], xr[i + 2].x, c0); c1 = fmaf(wr[i + 2], xr[i + 2].y, c1);
                d0 = fmaf(wr[i + 3], xr[i + 3].x, d0); d1 = fmaf(wr[i + 3], xr[i + 3].y, d1);
            }
        }
#pragma unroll
        for (int i = 96; i < 101; i++) {
            float wv = w[i * 275]; float2 x = x2[i];
            a0 = fmaf(wv, x.x, a0); a1 = fmaf(wv, x.y, a1);
        }
        s_hid[tid] = make_float2(tanhf((a0 + b0) + (c0 + d0)),
                                 tanhf((a1 + b1) + (c1 + d1)));
    }
    __syncthreads();

    // L2: 275 -> 275 (W2T global, k-split over 2 groups, both NK=138 via zero row)
    int g = tid / 144, j = tid - g * 144;
    bool act = (j < 138);
    int n0 = 2 * j;
    float4 acc = make_float4(0.f, 0.f, 0.f, 0.f);
    if (act) {
        acc = dotW2(g_W2T + (g * 138) * 276 + n0,
                    ((const float2*)(sm + OFF_HID)) + g * 138);
        if (g) s_p4[j] = acc;
    }
    __syncthreads();
    if (act && !g) {
        float4 p = s_p4[j];
        s_a2[n0]     = make_float2(tanhf(acc.x + p.x + rb2a), tanhf(acc.y + p.y + rb2a));
        s_a2[n0 + 1] = make_float2(tanhf(acc.z + p.z + rb2b), tanhf(acc.w + p.w + rb2b));
    }
    __syncthreads();

    // L3: 275 -> 100 (W3T in smem, k-split, both NK=138 via zero row), fused update
    float2 a3 = make_float2(0.f, 0.f);
    if (tid < 100) {
        a3 = dotW3(sm + OFF_W3T + tid, (const float2*)(sm + OFF_A2));
    } else if (tid < 200) {
        s_p2[tid - 100] = dotW3(sm + OFF_W3T + 138 * 100 + (tid - 100),
                                ((const float2*)(sm + OFF_A2)) + 138);
    }
    __syncthreads();
    if (tid < 100) {
        float2 pp = s_p2[tid];
        float2 f = make_float2(tanhf(a3.x + pp.x + rb3), tanhf(a3.y + pp.y + rb3));
        float2 y = s_y[tid];
        if (stage == 0) {
            s_ks[tid] = f;
            s_in[1 + tid] = make_float2(fmaf(0.5f * dt.x, f.x, y.x),
                                        fmaf(0.5f * dt.y, f.y, y.y));
        } else if (stage == 1) {
            float2 k = s_ks[tid];
            s_ks[tid] = make_float2(k.x + 2.f * f.x, k.y + 2.f * f.y);
            s_in[1 + tid] = make_float2(fmaf(0.5f * dt.x, f.x, y.x),
                                        fmaf(0.5f * dt.y, f.y, y.y));
        } else if (stage == 2) {
            float2 k = s_ks[tid];
            s_ks[tid] = make_float2(k.x + 2.f * f.x, k.y + 2.f * f.y);
            s_in[1 + tid] = make_float2(fmaf(dt.x, f.x, y.x),
                                        fmaf(dt.y, f.y, y.y));
        } else {
            float2 k = s_ks[tid];
            float2 yn = make_float2(y.x + dt.x * (k.x + f.x) / 6.f,
                                    y.y + dt.y * (k.y + f.y) / 6.f);
            s_y[tid] = yn;
            if (write_in) s_in[1 + tid] = yn;
        }
        if (tid == 0 && (stage < 3 || write_in)) s_in[0] = tnext;
    }
    __syncthreads();
}

// ---- RK4, NSUB=2 ----
__device__ __forceinline__ void integrate2(int tid, float* sm, float2 t0, float2 t1,
        float rb1, float rb2a, float rb2b, float rb3) {
    float2* s_in = (float2*)(sm + OFF_IN);
    float2* s_y  = (float2*)(sm + OFF_Y);
    float2 dt = make_float2((t1.x - t0.x) * 0.5f, (t1.y - t0.y) * 0.5f);
    if (tid < HH) s_in[1 + tid] = s_y[tid];
    if (tid == 0) s_in[0] = t0;
    __syncthreads();
#pragma unroll 1
    for (int st = 0; st < 8; st++) {
        int stage = st & 3, sub = st >> 2;
        float2 tb = make_float2(t0.x + sub * dt.x, t0.y + sub * dt.y);
        float2 tnext = (stage <= 1)
            ? make_float2(tb.x + 0.5f * dt.x, tb.y + 0.5f * dt.y)
            : make_float2(tb.x + dt.x, tb.y + dt.y);
        field_stage(tid, sm, stage, dt, tnext, (st == 3), rb1, rb2a, rb2b, rb3);
    }
}

// ---- prep: build transposed weight copies (with zero-pad rows) ----
__global__ void prep_kernel(const float* __restrict__ fW1, const float* __restrict__ fW2,
                            const float* __restrict__ fW3, const float* __restrict__ Whh,
                            const float* __restrict__ oW1, const float* __restrict__ oW2) {
    for (int i = blockIdx.x * blockDim.x + threadIdx.x; i < 174677;
         i += gridDim.x * blockDim.x) {
        if (i < 55376) {
            if (i < 27775) {
                int k = i / 275, n = i % 275;
                g_W13T[i] = fW1[n * 101 + k];
            } else if (i == 27775) {
                g_W13T[i] = 0.f;
            } else {
                int j = i - 27776, k = j / 100, n = j % 100;
                g_W13T[i] = (k < 275) ? fW3[n * 275 + k] : 0.f;
            }
        } else if (i < 131552) {
            int j = i - 55376, k = j / 276, n = j % 276;
            g_W2T[j] = (n < 275 && k < 275) ? fW2[n * 275 + k] : 0.f;
        } else if (i < 161552) {
            int j = i - 131552, k = j / 300, n = j % 300;
            g_WhhT[j] = Whh[n * 100 + k];
        } else if (i < 169052) {
            int j = i - 161552, k = j / 75, n = j % 75;
            g_oW1T[j] = oW1[n * 100 + k];
        } else {
            int j = i - 169052, k = j / 75, n = j % 75;
            g_oW2T[j] = oW2[n * 75 + k];
        }
    }
}

// ---- encode ----
__global__ void __launch_bounds__(NTHR, 1) encode_kernel(
        const float* __restrict__ past, const float* __restrict__ h0,
        const float* __restrict__ fb1, const float* __restrict__ fb2,
        const float* __restrict__ fb3,
        const float* __restrict__ Wih, const float* __restrict__ bih,
        const float* __restrict__ bhh) {
    extern __shared__ float sm[];
    int tid = threadIdx.x;
    int r0 = blockIdx.x * 2, r1 = r0 + 1;

    const float4* src = (const float4*)g_W13T;
    float4* dst = (float4*)sm;
    for (int i = tid; i < 55376 / 4; i += NTHR) dst[i] = src[i];

    float rb1 = (tid < NF) ? __ldg(fb1 + tid) : 0.f;
    int g = tid / 144, j = tid - g * 144;
    float rb2a = 0.f, rb2b = 0.f;
    if (g == 0 && j < 138) {
        rb2a = __ldg(fb2 + 2 * j);
        rb2b = (2 * j + 1 < NF) ? __ldg(fb2 + 2 * j + 1) : 0.f;
    }
    float rb3 = (tid < HH) ? __ldg(fb3 + tid) : 0.f;

    float2* s_y   = (float2*)(sm + OFF_Y);
    float2* s_u   = (float2*)(sm + OFF_HID);   // [200] aliased
    float2* s_inn = (float2*)(sm + OFF_A2);    // [100]
    float2* s_hn  = (float2*)(sm + OFF_PART);  // [100]
    if (tid < HH) s_y[tid] = make_float2(h0[r0 * HH + tid], h0[r1 * HH + tid]);
    if (tid == 0) ((float2*)(sm + OFF_HID))[275] = make_float2(0.f, 0.f);
    __syncthreads();

    float2 tprev = make_float2(0.f, 0.f);
    for (int step = 0; step < TP; step++) {
        float2 tcur = make_float2(past[(r0 * TP + step) * 2], past[(r1 * TP + step) * 2]);
        float2 t0 = (step == 0) ? make_float2(tcur.x - 1.f, tcur.y - 1.f) : tprev;
        integrate2(tid, sm, t0, tcur, rb1, rb2a, rb2b, rb3);

        float2 x = make_float2(past[(r0 * TP + step) * 2 + 1],
                               past[(r1 * TP + step) * 2 + 1]);
        const float4* y4 = (const float4*)(sm + OFF_Y);
        for (int jj = tid; jj < 300; jj += NTHR) {
            float bh = __ldg(bhh + jj);
            float a0 = bh, a1 = bh, b0 = 0.f, b1 = 0.f;
#pragma unroll 10
            for (int k = 0; k < 100; k += 2) {
                float w0 = __ldcg(g_WhhT + k * 300 + jj);
                float w1 = __ldcg(g_WhhT + (k + 1) * 300 + jj);
                float4 y = y4[k >> 1];
                a0 = fmaf(w0, y.x, a0); a1 = fmaf(w0, y.y, a1);
                b0 = fmaf(w1, y.z, b0); b1 = fmaf(w1, y.w, b1);
            }
            a0 += b0; a1 += b1;
            float wi = __ldg(Wih + jj), bi = __ldg(bih + jj);
            float2 gi = make_float2(fmaf(wi, x.x, bi), fmaf(wi, x.y, bi));
            if (jj < 200) s_u[jj] = make_float2(gi.x + a0, gi.y + a1);
            else { s_inn[jj - 200] = gi; s_hn[jj - 200] = make_float2(a0, a1); }
        }
        __syncthreads();
        if (tid < HH) {
            float2 u1 = s_u[tid], u2 = s_u[HH + tid];
            float2 gin = s_inn[tid], ghn = s_hn[tid], h = s_y[tid];
            float rx = sigm1(u1.x), ry = sigm1(u1.y);
            float zx = sigm1(u2.x), zy = sigm1(u2.y);
            float nx = tanhf(gin.x + rx * ghn.x), ny = tanhf(gin.y + ry * ghn.y);
            s_y[tid] = make_float2((1.f - zx) * nx + zx * h.x,
                                   (1.f - zy) * ny + zy * h.y);
        }
        __syncthreads();
        tprev = tcur;
    }
    if (tid < HH) {
        g_hB[r0 * HH + tid] = s_y[tid].x;
        g_hB[r1 * HH + tid] = s_y[tid].y;
    }
}

// ---- decoder head ----
__global__ void gx_kernel(const float* __restrict__ gW1, const float* __restrict__ gb1,
                          const float* __restrict__ gW2, const float* __restrict__ gb2,
                          const float* __restrict__ gW3, const float* __restrict__ gb3) {
    int b = blockIdx.x, tid = threadIdx.x;
    __shared__ float sh[HH], s1[HGG], s2[HGG];
    for (int k = tid; k < HH; k += blockDim.x) sh[k] = g_hB[b * HH + k];
    __syncthreads();
    if (tid < HGG) {
        float a = __ldg(gb1 + tid);
        const float* w = gW1 + tid * HH;
        for (int k = 0; k < HH; k++) a = fmaf(__ldg(w + k), sh[k], a);
        s1[tid] = leaky1(a);
    }
    __syncthreads();
    if (tid < HGG) {
        float a = __ldg(gb2 + tid);
        const float* w = gW2 + tid * HGG;
        for (int k = 0; k < HGG; k++) a = fmaf(__ldg(w + k), s1[k], a);
        s2[tid] = leaky1(a);
    }
    __syncthreads();
    if (tid < 2) {
        float a = __ldg(gb3 + tid);
        const float* w = gW3 + tid * HGG;
        for (int k = 0; k < HGG; k++) a = fmaf(__ldg(w + k), s2[k], a);
        g_gx[b * 2 + tid] = a;
    }
}

__global__ void z0_kernel(const float* __restrict__ eps) {
    int b = blockIdx.x, h = threadIdx.x;
    float loc, scale;
    if (b < NB / 2) {
        loc   = g_gx[(2 * b) * 2 + 0];
        scale = g_gx[(2 * b + 1) * 2 + 0];
    } else {
        int i = 2 * (b - NB / 2);
        loc   = fabsf(g_gx[i * 2 + 1]);
        scale = fabsf(g_gx[(i + 1) * 2 + 1]);
    }
    g_z0[b * HH + h] = loc + scale * eps[h * NB + b];
}

// ---- rollout output MLP ----
__device__ __forceinline__ void out_mlp(int tid, int s, int r0, int r1, float* sm,
        float rob1, float rob2,
        const float* __restrict__ oW3, const float* __restrict__ ob3,
        float* __restrict__ out) {
    float2* s_o1 = (float2*)(sm + OFF_HID);
    float2* s_o2 = (float2*)(sm + OFF_A2);
    if (tid < HOO) {
        const float4* y4 = (const float4*)(sm + OFF_Y);
        float a0 = rob1, a1 = rob1, b0 = 0.f, b1 = 0.f;
#pragma unroll 10
        for (int k = 0; k < 100; k += 2) {
            float w0 = __ldcg(g_oW1T + k * 75 + tid);
            float w1 = __ldcg(g_oW1T + (k + 1) * 75 + tid);
            float4 y = y4[k >> 1];
            a0 = fmaf(w0, y.x, a0); a1 = fmaf(w0, y.y, a1);
            b0 = fmaf(w1, y.z, b0); b1 = fmaf(w1, y.w, b1);
        }
        s_o1[tid] = make_float2(leaky1(a0 + b0), leaky1(a1 + b1));
    }
    __syncthreads();
    if (tid < HOO) {
        const float4* h4 = (const float4*)(sm + OFF_HID);
        float a0 = rob2, a1 = rob2, b0 = 0.f, b1 = 0.f;
#pragma unroll 8
        for (int k = 0; k + 1 < HOO; k += 2) {
            float w0 = __ldcg(g_oW2T + k * 75 + tid);
            float w1 = __ldcg(g_oW2T + (k + 1) * 75 + tid);
            float4 h = h4[k >> 1];
            a0 = fmaf(w0, h.x, a0); a1 = fmaf(w0, h.y, a1);
            b0 = fmaf(w1, h.z, b0); b1 = fmaf(w1, h.w, b1);
        }
        {
            float w0 = __ldcg(g_oW2T + 74 * 75 + tid);
            float2 h = s_o1[74];
            a0 = fmaf(w0, h.x, a0); a1 = fmaf(w0, h.y, a1);
        }
        s_o2[tid] = make_float2(leaky1(a0 + b0), leaky1(a1 + b1));
    }
    __syncthreads();
    if (tid < 32) {
        float a0 = 0.f, a1 = 0.f;
        for (int k = tid; k < HOO; k += 32) {
            float wv = __ldg(oW3 + k);
            float2 h = s_o2[k];
            a0 = fmaf(wv, h.x, a0); a1 = fmaf(wv, h.y, a1);
        }
#pragma unroll
        for (int o = 16; o; o >>= 1) {
            a0 += __shfl_down_sync(0xffffffffu, a0, o);
            a1 += __shfl_down_sync(0xffffffffu, a1, o);
        }
        if (tid == 0) {
            float b = __ldg(ob3);
            out[r0 * TFUT + s] = a0 + b;
            out[r1 * TFUT + s] = a1 + b;
        }
    }
    __syncthreads();
}

__global__ void __launch_bounds__(NTHR, 1) rollout_kernel(
        const float* __restrict__ tf_,
        const float* __restrict__ fb1, const float* __restrict__ fb2,
        const float* __restrict__ fb3,
        const float* __restrict__ ob1, const float* __restrict__ ob2,
        const float* __restrict__ oW3, const float* __restrict__ ob3,
        float* __restrict__ out) {
    extern __shared__ float sm[];
    int tid = threadIdx.x;
    int r0 = blockIdx.x * 2, r1 = r0 + 1;

    const float4* src = (const float4*)g_W13T;
    float4* dst = (float4*)sm;
    for (int i = tid; i < 55376 / 4; i += NTHR) dst[i] = src[i];

    float rb1 = (tid < NF) ? __ldg(fb1 + tid) : 0.f;
    int g = tid / 144, j = tid - g * 144;
    float rb2a = 0.f, rb2b = 0.f;
    if (g == 0 && j < 138) {
        rb2a = __ldg(fb2 + 2 * j);
        rb2b = (2 * j + 1 < NF) ? __ldg(fb2 + 2 * j + 1) : 0.f;
    }
    float rb3 = (tid < HH) ? __ldg(fb3 + tid) : 0.f;
    float rob1 = (tid < HOO) ? __ldg(ob1 + tid) : 0.f;
    float rob2 = (tid < HOO) ? __ldg(ob2 + tid) : 0.f;

    float2* s_y = (float2*)(sm + OFF_Y);
    if (tid < HH) s_y[tid] = make_float2(g_z0[r0 * HH + tid], g_z0[r1 * HH + tid]);
    if (tid == 0) ((float2*)(sm + OFF_HID))[275] = make_float2(0.f, 0.f);
    __syncthreads();

    out_mlp(tid, 0, r0, r1, sm, rob1, rob2, oW3, ob3, out);

    float2 tprev = make_float2(tf_[r0 * TFUT], tf_[r1 * TFUT]);
    for (int s = 1; s < TFUT; s++) {
        float2 tcur = make_float2(tf_[r0 * TFUT + s], tf_[r1 * TFUT + s]);
        integrate2(tid, sm, tprev, tcur, rb1, rb2a, rb2b, rb3);
        out_mlp(tid, s, r0, r1, sm, rob1, rob2, oW3, ob3, out);
        tprev = tcur;
    }
}

extern "C" void kernel_launch(void* const* d_in, const int* in_sizes, int n_in,
                              void* d_out, int out_size) {
    const float* past = (const float*)d_in[0];
    const float* h0   = (const float*)d_in[1];
    const float* t_fu = (const float*)d_in[2];
    const float* eps  = (const float*)d_in[3];
    const float* fW1  = (const float*)d_in[4];
    const float* fb1  = (const float*)d_in[5];
    const float* fW2  = (const float*)d_in[6];
    const float* fb2  = (const float*)d_in[7];
    const float* fW3  = (const float*)d_in[8];
    const float* fb3  = (const float*)d_in[9];
    const float* Wih  = (const float*)d_in[10];
    const float* Whh  = (const float*)d_in[11];
    const float* bih  = (const float*)d_in[12];
    const float* bhh  = (const float*)d_in[13];
    const float* gW1  = (const float*)d_in[14];
    const float* gb1  = (const float*)d_in[15];
    const float* gW2  = (const float*)d_in[16];
    const float* gb2  = (const float*)d_in[17];
    const float* gW3  = (const float*)d_in[18];
    const float* gb3  = (const float*)d_in[19];
    const float* oW1  = (const float*)d_in[20];
    const float* ob1  = (const float*)d_in[21];
    const float* oW2  = (const float*)d_in[22];
    const float* ob2  = (const float*)d_in[23];
    const float* oW3  = (const float*)d_in[24];
    const float* ob3  = (const float*)d_in[25];
    float* out = (float*)d_out;

    static bool attr_done = false;
    if (!attr_done) {
        cudaFuncSetAttribute(encode_kernel,
                             cudaFuncAttributeMaxDynamicSharedMemorySize, SMEM_BYTES);
        cudaFuncSetAttribute(rollout_kernel,
                             cudaFuncAttributeMaxDynamicSharedMemorySize, SMEM_BYTES);
        attr_done = true;
    }

    prep_kernel<<<192, 256>>>(fW1, fW2, fW3, Whh, oW1, oW2);
    encode_kernel<<<NCTA, NTHR, SMEM_BYTES>>>(past, h0, fb1, fb2, fb3, Wih, bih, bhh);
    gx_kernel<<<NB, 96>>>(gW1, gb1, gW2, gb2, gW3, gb3);
    z0_kernel<<<NB, HH>>>(eps);
    rollout_kernel<<<NCTA, NTHR, SMEM_BYTES>>>(t_fu, fb1, fb2, fb3,
                                               ob1, ob2, oW3, ob3, out);
}